// round 4
// baseline (speedup 1.0000x reference)
#include <cuda_runtime.h>
#include <cuda_bf16.h>
#include <cstdint>

// ============================================================================
// VQ-VAE quantizer, two-pass (sm_100-safe: warp-level mma.sync, no tcgen05):
//  Pass1: bf16 HMMA approx of S=z.e -> per-row candidate set within hard margin
//  Pass2: bitwise-exact d2 (XLA tree norms + sequential FMA dot) on candidates
// Output layout (float32): [ z_q_st (8388608) | loss (1) | idx (131072) ]
// ============================================================================

#define N_ROWS 131072
#define D      64
#define K      2048
#define TM     128          // rows per block
#define KCH    256          // codes per smem chunk
#define NCHUNK (K / KCH)    // 8
#define MARGIN 4.5e-4f      // deterministic bf16-GEMM + rounding cover

// smem (bytes): zbf [128][72] bf16 | Bt [256][72] bf16 | se [2048] f32
#define SM_ZBF  0
#define SM_BT   18432
#define SM_SE   (18432 + 36864)
#define SMEM1   (SM_SE + 8192)

__device__ float g_se[K];
__device__ float g_loss;
__device__ __align__(16) unsigned short g_eb[K * D];   // emb as bf16, row-major
__device__ int g_cnt[N_ROWS];
__device__ int g_ck[N_ROWS * 8];

// ---------------------------------------------------------------- exact math
__device__ __forceinline__ float tree32_sq(const float* __restrict__ x, int stride) {
    float l[32];
    #pragma unroll
    for (int t = 0; t < 32; t++) { float v = x[t * stride]; l[t] = __fmul_rn(v, v); }
    #pragma unroll
    for (int off = 16; off >= 1; off >>= 1)
        #pragma unroll
        for (int t = 0; t < 16; t++)
            if (t < off) l[t] = __fadd_rn(l[t], l[t + off]);
    return l[0];
}

__device__ __forceinline__ uint32_t pack_bf16x2(float lo, float hi) {
    __nv_bfloat162 h = __floats2bfloat162_rn(lo, hi);   // .x = lo half
    return *reinterpret_cast<uint32_t*>(&h);
}

// ---------------------------------------------------------------- prep
__global__ void zero_kernel() { g_loss = 0.0f; }

__global__ void emb_norm_kernel(const float* __restrict__ emb) {
    int k = blockIdx.x * blockDim.x + threadIdx.x;
    if (k < K)
        g_se[k] = __fadd_rn(tree32_sq(emb + k * D, 1), tree32_sq(emb + k * D + 32, 1));
}

__global__ void emb_prep_kernel(const float* __restrict__ emb) {
    int i = blockIdx.x * blockDim.x + threadIdx.x;
    if (i < K * D) {
        __nv_bfloat16 h = __float2bfloat16(emb[i]);
        g_eb[i] = *reinterpret_cast<unsigned short*>(&h);
    }
}

// ---------------------------------------------------------------- pass 1
// Candidate insert: slot is usable if its value is stale (>= limit).
#define CAND_INS(S, VAL, KK)                                                   \
    do {                                                                       \
        if ((VAL) < clim[S]) {                                                 \
            bool _ins = false;                                                 \
            _Pragma("unroll")                                                  \
            for (int _q = 0; _q < 4; _q++)                                     \
                if (!_ins && cv[S][_q] >= clim[S]) {                           \
                    cv[S][_q] = (VAL); ck[S][_q] = (KK); _ins = true;          \
                }                                                              \
            if (!_ins) covf |= (1 << (S));                                     \
            if ((VAL) < crm[S]) { crm[S] = (VAL); clim[S] = (VAL) + MARGIN; }  \
        }                                                                      \
    } while (0)

__global__ __launch_bounds__(256, 2)
void vq_pass1(const float* __restrict__ z_e) {
    extern __shared__ char smem[];
    __nv_bfloat16* zbf = (__nv_bfloat16*)(smem + SM_ZBF);   // [128][72]
    __nv_bfloat16* Bt  = (__nv_bfloat16*)(smem + SM_BT);    // [256][72]
    float* sse = (float*)(smem + SM_SE);

    const int tid = threadIdx.x;
    const int lane = tid & 31;
    const int wid = tid >> 5;
    const int rowbase = blockIdx.x * TM;

    // ---- stage z rows as bf16, padded stride 72 ----
    for (int i = tid; i < TM * 16; i += 256) {
        int r = i >> 4, c = (i & 15) * 4;
        float4 v = *(const float4*)(z_e + (size_t)(rowbase + r) * D + c);
        *(uint32_t*)&zbf[r * 72 + c]     = pack_bf16x2(v.x, v.y);
        *(uint32_t*)&zbf[r * 72 + c + 2] = pack_bf16x2(v.z, v.w);
    }
    for (int i = tid; i < K; i += 256) sse[i] = g_se[i];
    __syncthreads();

    // ---- A fragments (held whole kernel): warp = 16-row stripe ----
    const int r0 = wid * 16 + (lane >> 2);
    const int k0 = (lane & 3) * 2;
    uint32_t a[4][4];
    #pragma unroll
    for (int ks = 0; ks < 4; ks++) {
        a[ks][0] = *(uint32_t*)&zbf[r0 * 72 + ks * 16 + k0];
        a[ks][1] = *(uint32_t*)&zbf[(r0 + 8) * 72 + ks * 16 + k0];
        a[ks][2] = *(uint32_t*)&zbf[r0 * 72 + ks * 16 + k0 + 8];
        a[ks][3] = *(uint32_t*)&zbf[(r0 + 8) * 72 + ks * 16 + k0 + 8];
    }

    // ---- candidate state: 2 row-slots (r0, r0+8), 4 slots each ----
    float cv[2][4]; int ck[2][4];
    float crm[2], clim[2]; int covf = 0;
    #pragma unroll
    for (int s = 0; s < 2; s++) {
        crm[s] = 3.4e38f; clim[s] = 3.4e38f;
        #pragma unroll
        for (int q = 0; q < 4; q++) { cv[s][q] = 3.4e38f; ck[s][q] = 0; }
    }

    for (int ch = 0; ch < NCHUNK; ch++) {
        __syncthreads();   // Bt WAR (warp-synchronous mma: reads done at loop exit)
        // ---- stage chunk of 256 codes: 128B/row -> padded 144B rows ----
        {
            const uint4* src = (const uint4*)g_eb + (size_t)ch * KCH * 8;
            for (int i = tid; i < KCH * 8; i += 256) {
                int rr = i >> 3, j = i & 7;
                *(uint4*)&Bt[rr * 72 + j * 8] = src[rr * 8 + j];
            }
        }
        __syncthreads();

        const int nb = lane >> 2;   // B col within 8-tile
        for (int nt = 0; nt < 32; nt++) {
            float c[4] = {0.f, 0.f, 0.f, 0.f};
            const __nv_bfloat16* brow = &Bt[(nt * 8 + nb) * 72];
            #pragma unroll
            for (int ks = 0; ks < 4; ks++) {
                uint32_t b0 = *(uint32_t*)&brow[ks * 16 + k0];
                uint32_t b1 = *(uint32_t*)&brow[ks * 16 + k0 + 8];
                asm volatile(
                    "mma.sync.aligned.m16n8k16.row.col.f32.bf16.bf16.f32 "
                    "{%0,%1,%2,%3}, {%4,%5,%6,%7}, {%8,%9}, {%0,%1,%2,%3};"
                    : "+f"(c[0]), "+f"(c[1]), "+f"(c[2]), "+f"(c[3])
                    : "r"(a[ks][0]), "r"(a[ks][1]), "r"(a[ks][2]), "r"(a[ks][3]),
                      "r"(b0), "r"(b1));
            }
            // epilogue: metric = se_k - 2*S ; c0,c1 -> row r0; c2,c3 -> row r0+8
            const int colg = ch * KCH + nt * 8 + k0;
            float se0 = sse[colg], se1 = sse[colg + 1];
            float v00 = fmaf(c[0], -2.0f, se0);
            float v01 = fmaf(c[1], -2.0f, se1);
            float v10 = fmaf(c[2], -2.0f, se0);
            float v11 = fmaf(c[3], -2.0f, se1);
            CAND_INS(0, v00, colg);
            CAND_INS(0, v01, colg + 1);
            CAND_INS(1, v10, colg);
            CAND_INS(1, v11, colg + 1);
        }
    }

    // ---- merge across the 4 lanes sharing each row, write candidate lists ----
    const int lq = lane & 3;
    #pragma unroll
    for (int s = 0; s < 2; s++) {
        float gm = crm[s];
        gm = fminf(gm, __shfl_xor_sync(0xffffffffu, gm, 1));
        gm = fminf(gm, __shfl_xor_sync(0xffffffffu, gm, 2));
        float thr = gm + MARGIN;
        int cl = 0;
        #pragma unroll
        for (int q = 0; q < 4; q++) if (cv[s][q] <= thr) cl++;
        int o = (covf >> s) & 1;
        o |= __shfl_xor_sync(0xffffffffu, o, 1);
        o |= __shfl_xor_sync(0xffffffffu, o, 2);
        int base = lane & ~3;
        int c0 = __shfl_sync(0xffffffffu, cl, base);
        int c1 = __shfl_sync(0xffffffffu, cl, base + 1);
        int c2 = __shfl_sync(0xffffffffu, cl, base + 2);
        int c3 = __shfl_sync(0xffffffffu, cl, base + 3);
        int tot = c0 + c1 + c2 + c3;
        int off = (lq > 0 ? c0 : 0) + (lq > 1 ? c1 : 0) + (lq > 2 ? c2 : 0);
        int row = rowbase + wid * 16 + (lane >> 2) + s * 8;
        if (tot > 8 || o) {
            if (lq == 0) g_cnt[row] = 10000;
        } else {
            if (lq == 0) g_cnt[row] = tot;
            int w = 0;
            #pragma unroll
            for (int q = 0; q < 4; q++)
                if (cv[s][q] <= thr) { g_ck[row * 8 + off + w] = ck[s][q]; w++; }
        }
    }
}

// ---------------------------------------------------------------- pass 2
__global__ __launch_bounds__(128)
void vq_pass2(const float* __restrict__ z_e, const float* __restrict__ emb,
              float* __restrict__ out, int write_idx) {
    int row = blockIdx.x * 128 + threadIdx.x;
    const float* zr = z_e + (size_t)row * D;
    float A = __fadd_rn(tree32_sq(zr, 1), tree32_sq(zr + 32, 1));

    int cnt = g_cnt[row];
    float best = 3.4e38f;
    int bi = 0x7fffffff;
    if (cnt <= 8) {
        for (int i = 0; i < cnt; i++) {
            int k = g_ck[row * 8 + i];
            const float* ep = emb + k * D;
            float B = 0.0f;
            #pragma unroll
            for (int d = 0; d < D; d++) B = __fmaf_rn(zr[d], ep[d], B);
            float d2 = __fadd_rn(__fsub_rn(A, __fmul_rn(2.0f, B)), g_se[k]);
            if (d2 < best || (d2 == best && k < bi)) { best = d2; bi = k; }
        }
    } else {  // overflow fallback: exact full scan, first occurrence
        for (int k = 0; k < K; k++) {
            const float* ep = emb + k * D;
            float B = 0.0f;
            #pragma unroll
            for (int d = 0; d < D; d++) B = __fmaf_rn(zr[d], ep[d], B);
            float d2 = __fadd_rn(__fsub_rn(A, __fmul_rn(2.0f, B)), g_se[k]);
            if (d2 < best) { best = d2; bi = k; }
        }
    }

    const float* ep = emb + bi * D;
    float* orow = out + (size_t)row * D;
    float lacc = 0.0f;
    #pragma unroll
    for (int d = 0; d < D; d++) {
        float z = zr[d];
        float diff = __fsub_rn(ep[d], z);
        orow[d] = __fadd_rn(z, diff);
        lacc = __fmaf_rn(diff, diff, lacc);
    }
    if (write_idx) out[(size_t)N_ROWS * D + 1 + row] = (float)bi;

    #pragma unroll
    for (int m = 16; m >= 1; m >>= 1)
        lacc += __shfl_xor_sync(0xffffffffu, lacc, m);
    if ((threadIdx.x & 31) == 0) atomicAdd(&g_loss, lacc);
}

__global__ void finalize_kernel(float* __restrict__ out, int write_loss) {
    if (write_loss) {
        float m = g_loss / 8388608.0f;
        out[(size_t)N_ROWS * D] = __fadd_rn(__fmul_rn(0.25f, m), m);
    }
}

// ---------------------------------------------------------------- launch
extern "C" void kernel_launch(void* const* d_in, const int* in_sizes, int n_in,
                              void* d_out, int out_size) {
    const float* z_e = (const float*)d_in[0];
    const float* emb = (const float*)d_in[1];
    float* out = (float*)d_out;

    cudaFuncSetAttribute(vq_pass1, cudaFuncAttributeMaxDynamicSharedMemorySize, SMEM1);

    int write_loss = (out_size > N_ROWS * D) ? 1 : 0;
    int write_idx  = (out_size >= N_ROWS * D + 1 + N_ROWS) ? 1 : 0;

    zero_kernel<<<1, 1>>>();
    emb_norm_kernel<<<K / 256, 256>>>(emb);
    emb_prep_kernel<<<(K * D) / 256, 256>>>(emb);
    vq_pass1<<<N_ROWS / TM, 256, SMEM1>>>(z_e);
    vq_pass2<<<N_ROWS / 128, 128>>>(z_e, emb, out, write_idx);
    finalize_kernel<<<1, 1>>>(out, write_loss);
}

// round 5
// speedup vs baseline: 1.1719x; 1.1719x over previous
#include <cuda_runtime.h>
#include <cuda_bf16.h>
#include <cstdint>

// ============================================================================
// VQ-VAE quantizer, two-pass (sm_100-safe: warp-level mma.sync):
//  Pass1: bf16 HMMA approx of S=z.e -> per-row candidate set within hard
//         per-row margin (margin = ||z||*3.1e-5 + 2e-5, deterministic cover)
//  Pass2: bitwise-exact d2 (XLA tree norms + sequential FMA dot) on candidates
// Output layout (float32): [ z_q_st (8388608) | loss (1) | idx (131072) ]
// ============================================================================

#define N_ROWS 131072
#define D      64
#define K      2048
#define TM     128          // rows per block
#define KCH    128          // codes per smem chunk
#define NCHUNK (K / KCH)    // 16

// smem (bytes): zbf [128][72] bf16 | Bt [128][72] bf16 | se [2048] f32
#define SM_ZBF  0
#define SM_BT   18432
#define SM_SE   (18432 + 18432)
#define SMEM1   (SM_SE + 8192)

__device__ float g_se[K];
__device__ float g_sz[N_ROWS];
__device__ float g_loss;
__device__ __align__(16) unsigned short g_eb[K * D];   // emb as bf16, row-major
__device__ int g_cnt[N_ROWS];
__device__ int g_ck[N_ROWS * 8];

// ---------------------------------------------------------------- exact math
__device__ __forceinline__ float tree32_sq(const float* __restrict__ x, int stride) {
    float l[32];
    #pragma unroll
    for (int t = 0; t < 32; t++) { float v = x[t * stride]; l[t] = __fmul_rn(v, v); }
    #pragma unroll
    for (int off = 16; off >= 1; off >>= 1)
        #pragma unroll
        for (int t = 0; t < 16; t++)
            if (t < off) l[t] = __fadd_rn(l[t], l[t + off]);
    return l[0];
}

__device__ __forceinline__ uint32_t pack_bf16x2(float lo, float hi) {
    __nv_bfloat162 h = __floats2bfloat162_rn(lo, hi);   // .x = lo half
    return *reinterpret_cast<uint32_t*>(&h);
}

// ---------------------------------------------------------------- prep
__global__ void zero_kernel() { g_loss = 0.0f; }

__global__ void emb_norm_kernel(const float* __restrict__ emb) {
    int k = blockIdx.x * blockDim.x + threadIdx.x;
    if (k < K)
        g_se[k] = __fadd_rn(tree32_sq(emb + k * D, 1), tree32_sq(emb + k * D + 32, 1));
}

__global__ void z_norm_kernel(const float* __restrict__ z_e) {
    int r = blockIdx.x * blockDim.x + threadIdx.x;
    const float* zr = z_e + (size_t)r * D;
    g_sz[r] = __fadd_rn(tree32_sq(zr, 1), tree32_sq(zr + 32, 1));
}

__global__ void emb_prep_kernel(const float* __restrict__ emb) {
    int i = blockIdx.x * blockDim.x + threadIdx.x;
    if (i < K * D) {
        __nv_bfloat16 h = __float2bfloat16(emb[i]);
        g_eb[i] = *reinterpret_cast<unsigned short*>(&h);
    }
}

// ---------------------------------------------------------------- pass 1
// Candidate insert. Order matters: update running min/limit FIRST, then find a
// stale slot (cv >= clim). The true-argmin candidate always satisfies
// val <= final_min + margin <= clim(t) for all t, so it is inserted once and
// never counted stale -> never evicted. Overflow -> exact fallback in pass2.
#define CAND_INS(S, VAL, KK)                                                   \
    do {                                                                       \
        if ((VAL) < clim[S]) {                                                 \
            if ((VAL) < crm[S]) { crm[S] = (VAL); clim[S] = (VAL) + msl[S]; }  \
            bool _ins = false;                                                 \
            _Pragma("unroll")                                                  \
            for (int _q = 0; _q < 4; _q++)                                     \
                if (!_ins && cv[S][_q] >= clim[S]) {                           \
                    cv[S][_q] = (VAL); ck[S][_q] = (KK); _ins = true;          \
                }                                                              \
            if (!_ins) covf |= (1 << (S));                                     \
        }                                                                      \
    } while (0)

__global__ __launch_bounds__(256, 3)
void vq_pass1(const float* __restrict__ z_e) {
    extern __shared__ char smem[];
    __nv_bfloat16* zbf = (__nv_bfloat16*)(smem + SM_ZBF);   // [128][72]
    __nv_bfloat16* Bt  = (__nv_bfloat16*)(smem + SM_BT);    // [128][72]
    float* sse = (float*)(smem + SM_SE);

    const int tid = threadIdx.x;
    const int lane = tid & 31;
    const int wid = tid >> 5;
    const int rowbase = blockIdx.x * TM;

    // ---- stage z rows as bf16, padded stride 72 ----
    for (int i = tid; i < TM * 16; i += 256) {
        int r = i >> 4, c = (i & 15) * 4;
        float4 v = *(const float4*)(z_e + (size_t)(rowbase + r) * D + c);
        *(uint32_t*)&zbf[r * 72 + c]     = pack_bf16x2(v.x, v.y);
        *(uint32_t*)&zbf[r * 72 + c + 2] = pack_bf16x2(v.z, v.w);
    }
    for (int i = tid; i < K; i += 256) sse[i] = g_se[i];
    __syncthreads();

    // ---- A fragments (held whole kernel): warp = 16-row stripe ----
    const int r0 = wid * 16 + (lane >> 2);
    const int k0 = (lane & 3) * 2;
    uint32_t a[4][4];
    #pragma unroll
    for (int ks = 0; ks < 4; ks++) {
        a[ks][0] = *(uint32_t*)&zbf[r0 * 72 + ks * 16 + k0];
        a[ks][1] = *(uint32_t*)&zbf[(r0 + 8) * 72 + ks * 16 + k0];
        a[ks][2] = *(uint32_t*)&zbf[r0 * 72 + ks * 16 + k0 + 8];
        a[ks][3] = *(uint32_t*)&zbf[(r0 + 8) * 72 + ks * 16 + k0 + 8];
    }

    // ---- per-row hard margins from exact row norms ----
    float msl[2];
    msl[0] = __fmaf_rn(sqrtf(g_sz[rowbase + r0]),     3.1e-5f, 2.0e-5f);
    msl[1] = __fmaf_rn(sqrtf(g_sz[rowbase + r0 + 8]), 3.1e-5f, 2.0e-5f);

    // ---- candidate state: 2 row-slots (r0, r0+8), 4 slots each ----
    float cv[2][4]; int ck[2][4];
    float crm[2], clim[2]; int covf = 0;
    #pragma unroll
    for (int s = 0; s < 2; s++) {
        crm[s] = 3.4e38f; clim[s] = 3.4e38f;
        #pragma unroll
        for (int q = 0; q < 4; q++) { cv[s][q] = 3.4e38f; ck[s][q] = 0; }
    }

    for (int ch = 0; ch < NCHUNK; ch++) {
        __syncthreads();   // Bt WAR (warp-synchronous mma: reads done at loop exit)
        // ---- stage chunk of 128 codes: 128B/row -> padded 144B rows ----
        {
            const uint4* src = (const uint4*)g_eb + (size_t)ch * KCH * 8;
            for (int i = tid; i < KCH * 8; i += 256) {
                int rr = i >> 3, j = i & 7;
                *(uint4*)&Bt[rr * 72 + j * 8] = src[rr * 8 + j];
            }
        }
        __syncthreads();

        const int nb = lane >> 2;   // B col within 8-tile
        #pragma unroll 4
        for (int nt = 0; nt < 16; nt++) {
            float c[4] = {0.f, 0.f, 0.f, 0.f};
            const __nv_bfloat16* brow = &Bt[(nt * 8 + nb) * 72];
            #pragma unroll
            for (int ks = 0; ks < 4; ks++) {
                uint32_t b0 = *(uint32_t*)&brow[ks * 16 + k0];
                uint32_t b1 = *(uint32_t*)&brow[ks * 16 + k0 + 8];
                asm volatile(
                    "mma.sync.aligned.m16n8k16.row.col.f32.bf16.bf16.f32 "
                    "{%0,%1,%2,%3}, {%4,%5,%6,%7}, {%8,%9}, {%0,%1,%2,%3};"
                    : "+f"(c[0]), "+f"(c[1]), "+f"(c[2]), "+f"(c[3])
                    : "r"(a[ks][0]), "r"(a[ks][1]), "r"(a[ks][2]), "r"(a[ks][3]),
                      "r"(b0), "r"(b1));
            }
            // epilogue: metric = se_k - 2*S ; c0,c1 -> row r0; c2,c3 -> row r0+8
            const int colg = ch * KCH + nt * 8 + k0;
            float se0 = sse[colg], se1 = sse[colg + 1];
            float v00 = fmaf(c[0], -2.0f, se0);
            float v01 = fmaf(c[1], -2.0f, se1);
            float v10 = fmaf(c[2], -2.0f, se0);
            float v11 = fmaf(c[3], -2.0f, se1);
            CAND_INS(0, v00, colg);
            CAND_INS(0, v01, colg + 1);
            CAND_INS(1, v10, colg);
            CAND_INS(1, v11, colg + 1);
        }
    }

    // ---- merge across the 4 lanes sharing each row, write candidate lists ----
    const int lq = lane & 3;
    #pragma unroll
    for (int s = 0; s < 2; s++) {
        float gm = crm[s];
        gm = fminf(gm, __shfl_xor_sync(0xffffffffu, gm, 1));
        gm = fminf(gm, __shfl_xor_sync(0xffffffffu, gm, 2));
        float thr = gm + msl[s];
        int cl = 0;
        #pragma unroll
        for (int q = 0; q < 4; q++) if (cv[s][q] <= thr) cl++;
        int o = (covf >> s) & 1;
        o |= __shfl_xor_sync(0xffffffffu, o, 1);
        o |= __shfl_xor_sync(0xffffffffu, o, 2);
        int base = lane & ~3;
        int c0 = __shfl_sync(0xffffffffu, cl, base);
        int c1 = __shfl_sync(0xffffffffu, cl, base + 1);
        int c2 = __shfl_sync(0xffffffffu, cl, base + 2);
        int c3 = __shfl_sync(0xffffffffu, cl, base + 3);
        int tot = c0 + c1 + c2 + c3;
        int off = (lq > 0 ? c0 : 0) + (lq > 1 ? c1 : 0) + (lq > 2 ? c2 : 0);
        int row = rowbase + wid * 16 + (lane >> 2) + s * 8;
        if (tot > 8 || o) {
            if (lq == 0) g_cnt[row] = 10000;
        } else {
            if (lq == 0) g_cnt[row] = tot;
            int w = 0;
            #pragma unroll
            for (int q = 0; q < 4; q++)
                if (cv[s][q] <= thr) { g_ck[row * 8 + off + w] = ck[s][q]; w++; }
        }
    }
}

// ---------------------------------------------------------------- pass 2
__global__ __launch_bounds__(128)
void vq_pass2(const float* __restrict__ z_e, const float* __restrict__ emb,
              float* __restrict__ out, int write_idx) {
    int row = blockIdx.x * 128 + threadIdx.x;
    const float* zr = z_e + (size_t)row * D;
    float A = g_sz[row];

    int cnt = g_cnt[row];
    float best = 3.4e38f;
    int bi = 0x7fffffff;
    if (cnt <= 8) {
        for (int i = 0; i < cnt; i++) {
            int k = g_ck[row * 8 + i];
            const float* ep = emb + k * D;
            float B = 0.0f;
            #pragma unroll
            for (int d = 0; d < D; d++) B = __fmaf_rn(zr[d], ep[d], B);
            float d2 = __fadd_rn(__fsub_rn(A, __fmul_rn(2.0f, B)), g_se[k]);
            if (d2 < best || (d2 == best && k < bi)) { best = d2; bi = k; }
        }
    } else {  // overflow fallback: exact full scan, first occurrence
        for (int k = 0; k < K; k++) {
            const float* ep = emb + k * D;
            float B = 0.0f;
            #pragma unroll
            for (int d = 0; d < D; d++) B = __fmaf_rn(zr[d], ep[d], B);
            float d2 = __fadd_rn(__fsub_rn(A, __fmul_rn(2.0f, B)), g_se[k]);
            if (d2 < best) { best = d2; bi = k; }
        }
    }

    const float* ep = emb + bi * D;
    float* orow = out + (size_t)row * D;
    float lacc = 0.0f;
    #pragma unroll
    for (int d = 0; d < D; d++) {
        float z = zr[d];
        float diff = __fsub_rn(ep[d], z);
        orow[d] = __fadd_rn(z, diff);
        lacc = __fmaf_rn(diff, diff, lacc);
    }
    if (write_idx) out[(size_t)N_ROWS * D + 1 + row] = (float)bi;

    #pragma unroll
    for (int m = 16; m >= 1; m >>= 1)
        lacc += __shfl_xor_sync(0xffffffffu, lacc, m);
    if ((threadIdx.x & 31) == 0) atomicAdd(&g_loss, lacc);
}

__global__ void finalize_kernel(float* __restrict__ out, int write_loss) {
    if (write_loss) {
        float m = g_loss / 8388608.0f;
        out[(size_t)N_ROWS * D] = __fadd_rn(__fmul_rn(0.25f, m), m);
    }
}

// ---------------------------------------------------------------- launch
extern "C" void kernel_launch(void* const* d_in, const int* in_sizes, int n_in,
                              void* d_out, int out_size) {
    const float* z_e = (const float*)d_in[0];
    const float* emb = (const float*)d_in[1];
    float* out = (float*)d_out;

    cudaFuncSetAttribute(vq_pass1, cudaFuncAttributeMaxDynamicSharedMemorySize, SMEM1);

    int write_loss = (out_size > N_ROWS * D) ? 1 : 0;
    int write_idx  = (out_size >= N_ROWS * D + 1 + N_ROWS) ? 1 : 0;

    zero_kernel<<<1, 1>>>();
    emb_norm_kernel<<<K / 256, 256>>>(emb);
    z_norm_kernel<<<N_ROWS / 256, 256>>>(z_e);
    emb_prep_kernel<<<(K * D) / 256, 256>>>(emb);
    vq_pass1<<<N_ROWS / TM, 256, SMEM1>>>(z_e);
    vq_pass2<<<N_ROWS / 128, 128>>>(z_e, emb, out, write_idx);
    finalize_kernel<<<1, 1>>>(out, write_loss);
}